// round 6
// baseline (speedup 1.0000x reference)
#include <cuda_runtime.h>
#include <math.h>
#include <stdint.h>

// Problem constants
#define BB  2
#define SS  4096
#define DDIM 1024
#define HH  16
#define DHH 64
#define MM  (BB*SS)   // 8192 rows

// Scratch (allocation-free rule: __device__ globals)
__device__ float g_x[MM*DDIM];                 // tf32-rounded x
__device__ float g_Wt[4u*DDIM*DDIM];           // tf32-rounded W^T (q,k,v,o)
__device__ float g_Q[MM*DDIM];                 // tf32-rounded q
__device__ float g_K[MM*DDIM];                 // tf32-rounded k
__device__ float g_V[MM*DDIM];                 // tf32-rounded v
__device__ float g_ctx[MM*DDIM];               // tf32-rounded ctx

__device__ __forceinline__ float rna_tf32(float x) {
    uint32_t u;
    asm("cvt.rna.tf32.f32 %0, %1;" : "=r"(u) : "f"(x));
    return __uint_as_float(u);
}

__device__ __forceinline__ uint32_t smem_u32(const void* p) {
    uint32_t a;
    asm("{ .reg .u64 t; cvta.to.shared.u64 t, %1; cvt.u32.u64 %0, t; }"
        : "=r"(a) : "l"(p));
    return a;
}

__device__ __forceinline__ void cp_async16(uint32_t dst, const void* src) {
    asm volatile("cp.async.cg.shared.global [%0], [%1], 16;"
                 :: "r"(dst), "l"(src) : "memory");
}
#define CP_COMMIT() asm volatile("cp.async.commit_group;" ::: "memory")

#define MMA_TF32(c, a0, a1, a2, a3, b0, b1)                                    \
    asm volatile(                                                              \
        "mma.sync.aligned.m16n8k8.row.col.f32.tf32.tf32.f32 "                  \
        "{%0,%1,%2,%3},{%4,%5,%6,%7},{%8,%9},{%0,%1,%2,%3};"                   \
        : "+f"((c)[0]), "+f"((c)[1]), "+f"((c)[2]), "+f"((c)[3])               \
        : "r"(a0), "r"(a1), "r"(a2), "r"(a3), "r"(b0), "r"(b1))

// ===========================================================================
// Pre-pass kernels: tf32 RNA rounding (+ transpose for weights)
// ===========================================================================
__global__ __launch_bounds__(256) void round_x_kernel(const float* __restrict__ x)
{
    const size_t i = ((size_t)blockIdx.x * 256 + threadIdx.x) * 4;
    float4 v = *(const float4*)(x + i);
    v.x = rna_tf32(v.x); v.y = rna_tf32(v.y);
    v.z = rna_tf32(v.z); v.w = rna_tf32(v.w);
    *(float4*)(g_x + i) = v;
}

__global__ __launch_bounds__(256) void transpose_round_kernel(
    const float* __restrict__ Wq, const float* __restrict__ Wk,
    const float* __restrict__ Wv, const float* __restrict__ Wo)
{
    __shared__ float t[32][33];
    const int z = blockIdx.z;
    const float* W = (z == 0) ? Wq : (z == 1) ? Wk : (z == 2) ? Wv : Wo;
    float* Wt = g_Wt + (size_t)z * DDIM * DDIM;
    const int x0 = blockIdx.x * 32, y0 = blockIdx.y * 32;
    const int tx = threadIdx.x, ty = threadIdx.y;   // block (32,8)
#pragma unroll
    for (int i = 0; i < 4; i++) {
        const int row = ty + i * 8;
        t[row][tx] = W[(size_t)(y0 + row) * DDIM + x0 + tx];
    }
    __syncthreads();
#pragma unroll
    for (int i = 0; i < 4; i++) {
        const int row = ty + i * 8;
        Wt[(size_t)(x0 + row) * DDIM + y0 + tx] = rna_tf32(t[tx][row]);
    }
}

// ===========================================================================
// tf32 mma.sync GEMM (proven): C[8192,1024] = A @ Bt^T, CTA 128x128.
// ===========================================================================
#define GTM 128
#define GTN 128
#define GTK 32
#define STG_FLOATS 8192
#define GEMM_SMEM_BYTES (2 * STG_FLOATS * 4)   // 65536

__device__ __forceinline__ void gemm_mma_body(const float* __restrict__ A,
                                              const float* __restrict__ Bt,
                                              float* __restrict__ C,
                                              const float* __restrict__ bias,
                                              bool round_out)
{
    extern __shared__ float sm[];
    const int tid  = threadIdx.x;
    const int lane = tid & 31;
    const int warp = tid >> 5;
    const int wm   = warp >> 2;
    const int wn   = warp & 3;
    const int m0   = blockIdx.y * GTM;
    const int n0   = blockIdx.x * GTN;

    const int sr   = tid >> 3;
    const int kq   = tid & 7;
    const int ks_s = kq >> 1;
    const int half = kq & 1;
    const int g_s  = sr & 7;
    const int hi   = (sr >> 3) & 1;
    const int mtb  = sr >> 4;
    const int ntb  = sr >> 3;
    const int le0 = g_s * 4 + (0 ^ ks_s);
    const int le1 = g_s * 4 + (1 ^ ks_s);
    const int le2 = g_s * 4 + (2 ^ ks_s);
    const int le3 = g_s * 4 + (3 ^ ks_s);

    const float* ga = A  + (size_t)(m0 + sr) * DDIM + kq * 4;
    const float* gb = Bt + (size_t)(n0 + sr) * DDIM + kq * 4;

    float acc[16][4];
#pragma unroll
    for (int t = 0; t < 16; t++)
#pragma unroll
        for (int e = 0; e < 4; e++) acc[t][e] = 0.f;

    float4 ra[4], rb[4];

#define LDG_CHUNK(kc)                                                          \
    {                                                                          \
        _Pragma("unroll")                                                      \
        for (int i = 0; i < 4; i++) {                                          \
            ra[i] = *(const float4*)(ga + (size_t)(i * 32) * DDIM + (kc));     \
            rb[i] = *(const float4*)(gb + (size_t)(i * 32) * DDIM + (kc));     \
        }                                                                      \
    }

#define STS_CHUNK(s)                                                           \
    {                                                                          \
        float* sAp = sm + (s) * STG_FLOATS;                                    \
        float* sBp = sAp + 4096;                                               \
        _Pragma("unroll")                                                      \
        for (int i = 0; i < 4; i++) {                                          \
            float* da = sAp + (ks_s * 8 + i * 2 + mtb) * 128 + half * 2 + hi;  \
            da[le0 * 4] = ra[i].x;                                             \
            da[le1 * 4] = ra[i].y;                                             \
            da[le2 * 4] = ra[i].z;                                             \
            da[le3 * 4] = ra[i].w;                                             \
            float* db = sBp + (ks_s * 16 + i * 4 + ntb) * 64 + half;           \
            db[le0 * 2] = rb[i].x;                                             \
            db[le1 * 2] = rb[i].y;                                             \
            db[le2 * 2] = rb[i].z;                                             \
            db[le3 * 2] = rb[i].w;                                             \
        }                                                                      \
    }

    LDG_CHUNK(0);
    STS_CHUNK(0);
    __syncthreads();

    for (int it = 0; it < 32; ++it) {
        if (it < 31) LDG_CHUNK((it + 1) * GTK);

        const float* sAc = sm + (it & 1) * STG_FLOATS;
        const float* sBc = sAc + 4096;

#pragma unroll
        for (int ks = 0; ks < 4; ks++) {
            const int lsw = lane ^ ks;
            uint32_t af[4][4];
            uint32_t bf[4][2];
#pragma unroll
            for (int i = 0; i < 4; i++) {
                float4 av = *(const float4*)&sAc[((ks * 8 + wm * 4 + i) * 32 + lsw) * 4];
                af[i][0] = __float_as_uint(av.x);
                af[i][1] = __float_as_uint(av.y);
                af[i][2] = __float_as_uint(av.z);
                af[i][3] = __float_as_uint(av.w);
            }
#pragma unroll
            for (int j = 0; j < 4; j++) {
                float2 bv = *(const float2*)&sBc[((ks * 16 + wn * 4 + j) * 32 + lsw) * 2];
                bf[j][0] = __float_as_uint(bv.x);
                bf[j][1] = __float_as_uint(bv.y);
            }
#pragma unroll
            for (int i = 0; i < 4; i++)
#pragma unroll
                for (int j = 0; j < 4; j++)
                    MMA_TF32(acc[i * 4 + j],
                             af[i][0], af[i][1], af[i][2], af[i][3],
                             bf[j][0], bf[j][1]);
        }

        if (it < 31) STS_CHUNK((it + 1) & 1);
        __syncthreads();
    }

    const int g   = lane >> 2;
    const int cth = lane & 3;
#pragma unroll
    for (int i = 0; i < 4; i++) {
        const int row = m0 + wm * 64 + i * 16 + g;
#pragma unroll
        for (int j = 0; j < 4; j++) {
            const int col = n0 + wn * 32 + j * 8 + cth * 2;
            float2 v0 = make_float2(acc[i * 4 + j][0], acc[i * 4 + j][1]);
            float2 v1 = make_float2(acc[i * 4 + j][2], acc[i * 4 + j][3]);
            if (bias != nullptr) {
                const float b0 = bias[col], b1 = bias[col + 1];
                v0.x += b0; v0.y += b1;
                v1.x += b0; v1.y += b1;
            }
            if (round_out) {
                v0.x = rna_tf32(v0.x); v0.y = rna_tf32(v0.y);
                v1.x = rna_tf32(v1.x); v1.y = rna_tf32(v1.y);
            }
            *(float2*)&C[(size_t)row * DDIM + col]       = v0;
            *(float2*)&C[(size_t)(row + 8) * DDIM + col] = v1;
        }
    }
#undef LDG_CHUNK
#undef STS_CHUNK
}

__global__ __launch_bounds__(256, 1) void qkv_mma_kernel()
{
    const float* Bt = g_Wt + (size_t)blockIdx.z * DDIM * DDIM;
    float* Cp = (blockIdx.z == 0) ? g_Q : (blockIdx.z == 1) ? g_K : g_V;
    gemm_mma_body(g_x, Bt, Cp, nullptr, true);
}

__global__ __launch_bounds__(256, 1) void out_mma_kernel(const float* __restrict__ bo,
                                                         float* __restrict__ out)
{
    gemm_mma_body(g_ctx, g_Wt + 3ull * DDIM * DDIM, out, bo, false);
}

// ===========================================================================
// tf32 mma.sync causal flash attention, fragment-order K/V staging.
// CTA: 128 queries x one (b,h), 256 threads (8 warps x 16 q-rows).
// K-block = 64 keys. K and V stored in smem in MMA B-fragment order:
//   s[ks][nt][pos], pos = ((r^x)*4 + (c^x))*2 + slot, x = ks&3
// so each MMA's {b0,b1} is one conflict-free LDS.64.
// Register double-buffered LDG->STS producer; ONE __syncthreads per k-block.
// ===========================================================================
#define NEG_BIG (-1e30f)
#define AT_STAGE_F 8192                      // K frags 4096 + V frags 4096
#define ATT_SMEM_BYTES (2 * AT_STAGE_F * 4)  // 65536

__global__ __launch_bounds__(256, 1) void attn_mma_kernel()
{
    extern __shared__ float smf[];
    const uint32_t sb = smem_u32(smf);
    const int tid = threadIdx.x, lane = tid & 31, warp = tid >> 5;
    const int bh = blockIdx.y, b = bh >> 4, h = bh & 15;
    const int qt = (int)gridDim.x - 1 - (int)blockIdx.x;   // heavy first
    const int q0 = qt * 128;
    const int qw0 = q0 + warp * 16;
    const int nb = 2 * qt + 2;
    const int r = lane >> 2, c = lane & 3;

    const float* gq  = g_Q + (size_t)(b * SS + q0) * DDIM + h * DHH;
    const float* gk0 = g_K + (size_t)(b * SS) * DDIM + h * DHH;
    const float* gv0 = g_V + (size_t)(b * SS) * DDIM + h * DHH;

    // consumer lane offsets per (ks&3)
    int lp4[4];
#pragma unroll
    for (int xx = 0; xx < 4; xx++)
        lp4[xx] = (((r ^ xx) << 2) + (c ^ xx)) << 1;

    // ---- stage Q (128x64 row-major, 32KB = stage 0) then build A-frags ----
#pragma unroll
    for (int i = 0; i < 8; i++) {
        const int ch = tid + i * 256;
        cp_async16(sb + ch * 16, gq + (size_t)(ch >> 4) * DDIM + (ch & 15) * 4);
    }
    CP_COMMIT();
    asm volatile("cp.async.wait_group 0;" ::: "memory");
    __syncthreads();

    uint32_t qa[8][4];
#pragma unroll
    for (int ks = 0; ks < 8; ks++) {
        const float* qs = smf + (warp * 16 + r) * 64 + ks * 8 + c;
        qa[ks][0] = __float_as_uint(qs[0] * 0.125f);
        qa[ks][1] = __float_as_uint(qs[8 * 64] * 0.125f);
        qa[ks][2] = __float_as_uint(qs[4] * 0.125f);
        qa[ks][3] = __float_as_uint(qs[8 * 64 + 4] * 0.125f);
    }
    __syncthreads();

    // ---- loader constants ----
    const int vkey  = tid & 63;
    const int vks   = vkey >> 3, vcc = vkey & 3, vslot = (vkey >> 2) & 1;
    const int vx    = vks & 3;
    const int vbase = vks * 512 + vslot + ((vcc ^ vx) << 1);   // + nt*64 + (r^vx)*8
    const float* gvrow = gv0;  // + key row resolved below per block

    float4 rK[4], rV[4];

#define AT_LDG(kb)                                                             \
    {                                                                          \
        const float* gk = gk0 + (size_t)(kb) * 64 * DDIM;                      \
        const float* gv = gv0 + (size_t)(kb) * 64 * DDIM;                      \
        _Pragma("unroll")                                                      \
        for (int i = 0; i < 4; i++) {                                          \
            const int ch = tid + i * 256;                                      \
            rK[i] = *(const float4*)(gk + (size_t)(ch >> 4) * DDIM + (ch & 15) * 4); \
            rV[i] = *(const float4*)(gv + (size_t)vkey * DDIM                  \
                                     + ((tid >> 6) + i * 4) * 4);              \
        }                                                                      \
    }

#define AT_STS_K(s)                                                            \
    {                                                                          \
        float* dst = smf + (s) * AT_STAGE_F;                                   \
        _Pragma("unroll")                                                      \
        for (int i = 0; i < 4; i++) {                                          \
            const int ch = tid + i * 256;                                      \
            const int key = ch >> 4, c16 = ch & 15;                            \
            const int ks = c16 >> 1, slot = c16 & 1, x = ks & 3;               \
            const int rr = (key & 7) ^ x;                                      \
            float* p = dst + ks * 512 + (key >> 3) * 64 + slot + (rr << 3);    \
            p[(0 ^ x) << 1] = rK[i].x;                                         \
            p[(1 ^ x) << 1] = rK[i].y;                                         \
            p[(2 ^ x) << 1] = rK[i].z;                                         \
            p[(3 ^ x) << 1] = rK[i].w;                                         \
        }                                                                      \
    }

#define AT_STS_V(s)                                                            \
    {                                                                          \
        float* dstv = smf + (s) * AT_STAGE_F + 4096 + vbase;                   \
        _Pragma("unroll")                                                      \
        for (int i = 0; i < 4; i++) {                                          \
            const int c16 = (tid >> 6) + i * 4;                                \
            const int rb = (c16 & 1) << 2;                                     \
            float* q = dstv + (c16 >> 1) * 64;                                 \
            q[((rb + 0) ^ vx) << 3] = rV[i].x;                                 \
            q[((rb + 1) ^ vx) << 3] = rV[i].y;                                 \
            q[((rb + 2) ^ vx) << 3] = rV[i].z;                                 \
            q[((rb + 3) ^ vx) << 3] = rV[i].w;                                 \
        }                                                                      \
    }

    // preload k-block 0 into stage 0
    AT_LDG(0);
    AT_STS_K(0);
    AT_STS_V(0);
    __syncthreads();

    float O[8][4];
#pragma unroll
    for (int t = 0; t < 8; t++)
#pragma unroll
        for (int e = 0; e < 4; e++) O[t][e] = 0.f;
    float m0v = NEG_BIG, m1v = NEG_BIG, l0v = 0.f, l1v = 0.f;

    const int l0p = (lane & 28) | ((lane & 3) >> 1);
    const int l2p = l0p + 2;
    const bool odd = (lane & 1) != 0;

    for (int kb = 0; kb < nb; kb++) {
        const bool haveNext = (kb + 1 < nb);
        if (haveNext) AT_LDG(kb + 1);

        const int k0 = kb * 64;
        const bool active = (k0 <= qw0 + 15);
        const float* Ksm = smf + (kb & 1) * AT_STAGE_F;
        const float* Vsm = Ksm + 4096;

        float s[8][4];
        if (active) {
            // ---- S = Q K^T ----
#pragma unroll
            for (int t = 0; t < 8; t++)
#pragma unroll
                for (int e = 0; e < 4; e++) s[t][e] = 0.f;

#pragma unroll
            for (int ks = 0; ks < 8; ks++) {
                const float* kbp = Ksm + ks * 512 + lp4[ks & 3];
#pragma unroll
                for (int nt = 0; nt < 8; nt++) {
                    const float2 kf = *(const float2*)(kbp + nt * 64);
                    MMA_TF32(s[nt], qa[ks][0], qa[ks][1], qa[ks][2], qa[ks][3],
                             __float_as_uint(kf.x), __float_as_uint(kf.y));
                }
            }

            // ---- causal mask (diagonal blocks only) ----
            if (k0 + 63 > qw0) {
                const int qlo = qw0 + r, qhi = qlo + 8;
#pragma unroll
                for (int nt = 0; nt < 8; nt++) {
                    const int key0 = k0 + nt * 8 + 2 * c;
                    if (key0     > qlo) s[nt][0] = NEG_BIG;
                    if (key0 + 1 > qlo) s[nt][1] = NEG_BIG;
                    if (key0     > qhi) s[nt][2] = NEG_BIG;
                    if (key0 + 1 > qhi) s[nt][3] = NEG_BIG;
                }
            }
        }

        if (haveNext) AT_STS_K((kb + 1) & 1);

        if (active) {
            // ---- online softmax ----
            float cl = NEG_BIG, chv = NEG_BIG;
#pragma unroll
            for (int nt = 0; nt < 8; nt++) {
                cl  = fmaxf(cl,  fmaxf(s[nt][0], s[nt][1]));
                chv = fmaxf(chv, fmaxf(s[nt][2], s[nt][3]));
            }
            cl  = fmaxf(cl,  __shfl_xor_sync(0xffffffffu, cl, 1));
            cl  = fmaxf(cl,  __shfl_xor_sync(0xffffffffu, cl, 2));
            chv = fmaxf(chv, __shfl_xor_sync(0xffffffffu, chv, 1));
            chv = fmaxf(chv, __shfl_xor_sync(0xffffffffu, chv, 2));
            const float mn0 = fmaxf(m0v, cl), mn1 = fmaxf(m1v, chv);
            const float corr0 = __expf(m0v - mn0), corr1 = __expf(m1v - mn1);
            m0v = mn0; m1v = mn1;

            float sl = 0.f, sh = 0.f;
#pragma unroll
            for (int nt = 0; nt < 8; nt++) {
                s[nt][0] = __expf(s[nt][0] - mn0); sl += s[nt][0];
                s[nt][1] = __expf(s[nt][1] - mn0); sl += s[nt][1];
                s[nt][2] = __expf(s[nt][2] - mn1); sh += s[nt][2];
                s[nt][3] = __expf(s[nt][3] - mn1); sh += s[nt][3];
            }
            sl += __shfl_xor_sync(0xffffffffu, sl, 1);
            sl += __shfl_xor_sync(0xffffffffu, sl, 2);
            sh += __shfl_xor_sync(0xffffffffu, sh, 1);
            sh += __shfl_xor_sync(0xffffffffu, sh, 2);
            l0v = l0v * corr0 + sl;
            l1v = l1v * corr1 + sh;

#pragma unroll
            for (int nt = 0; nt < 8; nt++) {
                O[nt][0] *= corr0; O[nt][1] *= corr0;
                O[nt][2] *= corr1; O[nt][3] *= corr1;
                s[nt][0] = rna_tf32(s[nt][0]); s[nt][1] = rna_tf32(s[nt][1]);
                s[nt][2] = rna_tf32(s[nt][2]); s[nt][3] = rna_tf32(s[nt][3]);
            }

            // ---- O += P V : shuffle C-frags -> A-frags, then mma ----
#pragma unroll
            for (int ks = 0; ks < 8; ks++) {
                const float e0 = __shfl_sync(0xffffffffu, s[ks][0], l0p);
                const float o0 = __shfl_sync(0xffffffffu, s[ks][1], l0p);
                const float e2 = __shfl_sync(0xffffffffu, s[ks][0], l2p);
                const float o2 = __shfl_sync(0xffffffffu, s[ks][1], l2p);
                const float e1 = __shfl_sync(0xffffffffu, s[ks][2], l0p);
                const float o1 = __shfl_sync(0xffffffffu, s[ks][3], l0p);
                const float e3 = __shfl_sync(0xffffffffu, s[ks][2], l2p);
                const float o3 = __shfl_sync(0xffffffffu, s[ks][3], l2p);
                const uint32_t a0 = __float_as_uint(odd ? o0 : e0);
                const uint32_t a1 = __float_as_uint(odd ? o1 : e1);
                const uint32_t a2 = __float_as_uint(odd ? o2 : e2);
                const uint32_t a3 = __float_as_uint(odd ? o3 : e3);
                const float* vbp = Vsm + ks * 512 + lp4[ks & 3];
#pragma unroll
                for (int nt = 0; nt < 8; nt++) {
                    const float2 vf = *(const float2*)(vbp + nt * 64);
                    MMA_TF32(O[nt], a0, a1, a2, a3,
                             __float_as_uint(vf.x), __float_as_uint(vf.y));
                }
            }
        }

        if (haveNext) AT_STS_V((kb + 1) & 1);
        __syncthreads();
    }

    // ---- epilogue: normalize, rna-round (feeds tf32 out-proj), store ----
    const float inv0 = 1.f / l0v, inv1 = 1.f / l1v;
    const size_t row0 = (size_t)(b * SS + qw0 + r);
#pragma unroll
    for (int nt = 0; nt < 8; nt++) {
        const int col = h * DHH + nt * 8 + 2 * c;
        float2 w0 = make_float2(rna_tf32(O[nt][0] * inv0), rna_tf32(O[nt][1] * inv0));
        float2 w1 = make_float2(rna_tf32(O[nt][2] * inv1), rna_tf32(O[nt][3] * inv1));
        *(float2*)&g_ctx[row0 * DDIM + col]       = w0;
        *(float2*)&g_ctx[(row0 + 8) * DDIM + col] = w1;
    }
    (void)gvrow;
#undef AT_LDG
#undef AT_STS_K
#undef AT_STS_V
}

// ===========================================================================
extern "C" void kernel_launch(void* const* d_in, const int* in_sizes, int n_in,
                              void* d_out, int out_size)
{
    (void)in_sizes; (void)n_in; (void)out_size;
    const float* x  = (const float*)d_in[0];
    const float* Wq = (const float*)d_in[1];
    const float* Wk = (const float*)d_in[2];
    const float* Wv = (const float*)d_in[3];
    const float* Wo = (const float*)d_in[4];
    const float* bo = (const float*)d_in[5];
    float* out = (float*)d_out;

    cudaFuncSetAttribute(qkv_mma_kernel, cudaFuncAttributeMaxDynamicSharedMemorySize,
                         GEMM_SMEM_BYTES);
    cudaFuncSetAttribute(out_mma_kernel, cudaFuncAttributeMaxDynamicSharedMemorySize,
                         GEMM_SMEM_BYTES);
    cudaFuncSetAttribute(attn_mma_kernel, cudaFuncAttributeMaxDynamicSharedMemorySize,
                         ATT_SMEM_BYTES);

    round_x_kernel<<<(MM * DDIM) / (256 * 4), 256>>>(x);
    transpose_round_kernel<<<dim3(32, 32, 4), dim3(32, 8)>>>(Wq, Wk, Wv, Wo);

    qkv_mma_kernel<<<dim3(DDIM / GTN, MM / GTM, 3), 256, GEMM_SMEM_BYTES>>>();

    attn_mma_kernel<<<dim3(SS / 128, BB * HH), 256, ATT_SMEM_BYTES>>>();

    out_mma_kernel<<<dim3(DDIM / GTN, MM / GTM), 256, GEMM_SMEM_BYTES>>>(bo, out);
}

// round 7
// speedup vs baseline: 1.0949x; 1.0949x over previous
#include <cuda_runtime.h>
#include <math.h>
#include <stdint.h>

// Problem constants
#define BB  2
#define SS  4096
#define DDIM 1024
#define HH  16
#define DHH 64
#define MM  (BB*SS)   // 8192 rows

// Scratch (allocation-free rule: __device__ globals)
__device__ float g_x[MM*DDIM];                 // tf32-rounded x
__device__ float g_Wt[4u*DDIM*DDIM];           // tf32-rounded W^T (q,k,v,o)
__device__ float g_Q[MM*DDIM];                 // tf32-rounded q
__device__ float g_K[MM*DDIM];                 // tf32-rounded k
__device__ float g_V[MM*DDIM];                 // tf32-rounded v
__device__ float g_ctx[MM*DDIM];               // tf32-rounded ctx

__device__ __forceinline__ float rna_tf32(float x) {
    uint32_t u;
    asm("cvt.rna.tf32.f32 %0, %1;" : "=r"(u) : "f"(x));
    return __uint_as_float(u);
}

__device__ __forceinline__ uint32_t smem_u32(const void* p) {
    uint32_t a;
    asm("{ .reg .u64 t; cvta.to.shared.u64 t, %1; cvt.u32.u64 %0, t; }"
        : "=r"(a) : "l"(p));
    return a;
}

__device__ __forceinline__ void cp_async16(uint32_t dst, const void* src) {
    asm volatile("cp.async.cg.shared.global [%0], [%1], 16;"
                 :: "r"(dst), "l"(src) : "memory");
}
#define CP_COMMIT() asm volatile("cp.async.commit_group;" ::: "memory")

#define MMA_TF32(c, a0, a1, a2, a3, b0, b1)                                    \
    asm volatile(                                                              \
        "mma.sync.aligned.m16n8k8.row.col.f32.tf32.tf32.f32 "                  \
        "{%0,%1,%2,%3},{%4,%5,%6,%7},{%8,%9},{%0,%1,%2,%3};"                   \
        : "+f"((c)[0]), "+f"((c)[1]), "+f"((c)[2]), "+f"((c)[3])               \
        : "r"(a0), "r"(a1), "r"(a2), "r"(a3), "r"(b0), "r"(b1))

// ===========================================================================
// Pre-pass kernels: tf32 RNA rounding (+ transpose for weights)
// ===========================================================================
__global__ __launch_bounds__(256) void round_x_kernel(const float* __restrict__ x)
{
    const size_t i = ((size_t)blockIdx.x * 256 + threadIdx.x) * 4;
    float4 v = *(const float4*)(x + i);
    v.x = rna_tf32(v.x); v.y = rna_tf32(v.y);
    v.z = rna_tf32(v.z); v.w = rna_tf32(v.w);
    *(float4*)(g_x + i) = v;
}

__global__ __launch_bounds__(256) void transpose_round_kernel(
    const float* __restrict__ Wq, const float* __restrict__ Wk,
    const float* __restrict__ Wv, const float* __restrict__ Wo)
{
    __shared__ float t[32][33];
    const int z = blockIdx.z;
    const float* W = (z == 0) ? Wq : (z == 1) ? Wk : (z == 2) ? Wv : Wo;
    float* Wt = g_Wt + (size_t)z * DDIM * DDIM;
    const int x0 = blockIdx.x * 32, y0 = blockIdx.y * 32;
    const int tx = threadIdx.x, ty = threadIdx.y;   // block (32,8)
#pragma unroll
    for (int i = 0; i < 4; i++) {
        const int row = ty + i * 8;
        t[row][tx] = W[(size_t)(y0 + row) * DDIM + x0 + tx];
    }
    __syncthreads();
#pragma unroll
    for (int i = 0; i < 4; i++) {
        const int row = ty + i * 8;
        Wt[(size_t)(x0 + row) * DDIM + y0 + tx] = rna_tf32(t[tx][row]);
    }
}

// ===========================================================================
// tf32 mma.sync GEMM (proven): C[8192,1024] = A @ Bt^T, CTA 128x128.
// ===========================================================================
#define GTM 128
#define GTN 128
#define GTK 32
#define STG_FLOATS 8192
#define GEMM_SMEM_BYTES (2 * STG_FLOATS * 4)   // 65536

__device__ __forceinline__ void gemm_mma_body(const float* __restrict__ A,
                                              const float* __restrict__ Bt,
                                              float* __restrict__ C,
                                              const float* __restrict__ bias,
                                              bool round_out)
{
    extern __shared__ float sm[];
    const int tid  = threadIdx.x;
    const int lane = tid & 31;
    const int warp = tid >> 5;
    const int wm   = warp >> 2;
    const int wn   = warp & 3;
    const int m0   = blockIdx.y * GTM;
    const int n0   = blockIdx.x * GTN;

    const int sr   = tid >> 3;
    const int kq   = tid & 7;
    const int ks_s = kq >> 1;
    const int half = kq & 1;
    const int g_s  = sr & 7;
    const int hi   = (sr >> 3) & 1;
    const int mtb  = sr >> 4;
    const int ntb  = sr >> 3;
    const int le0 = g_s * 4 + (0 ^ ks_s);
    const int le1 = g_s * 4 + (1 ^ ks_s);
    const int le2 = g_s * 4 + (2 ^ ks_s);
    const int le3 = g_s * 4 + (3 ^ ks_s);

    const float* ga = A  + (size_t)(m0 + sr) * DDIM + kq * 4;
    const float* gb = Bt + (size_t)(n0 + sr) * DDIM + kq * 4;

    float acc[16][4];
#pragma unroll
    for (int t = 0; t < 16; t++)
#pragma unroll
        for (int e = 0; e < 4; e++) acc[t][e] = 0.f;

    float4 ra[4], rb[4];

#define LDG_CHUNK(kc)                                                          \
    {                                                                          \
        _Pragma("unroll")                                                      \
        for (int i = 0; i < 4; i++) {                                          \
            ra[i] = *(const float4*)(ga + (size_t)(i * 32) * DDIM + (kc));     \
            rb[i] = *(const float4*)(gb + (size_t)(i * 32) * DDIM + (kc));     \
        }                                                                      \
    }

#define STS_CHUNK(s)                                                           \
    {                                                                          \
        float* sAp = sm + (s) * STG_FLOATS;                                    \
        float* sBp = sAp + 4096;                                               \
        _Pragma("unroll")                                                      \
        for (int i = 0; i < 4; i++) {                                          \
            float* da = sAp + (ks_s * 8 + i * 2 + mtb) * 128 + half * 2 + hi;  \
            da[le0 * 4] = ra[i].x;                                             \
            da[le1 * 4] = ra[i].y;                                             \
            da[le2 * 4] = ra[i].z;                                             \
            da[le3 * 4] = ra[i].w;                                             \
            float* db = sBp + (ks_s * 16 + i * 4 + ntb) * 64 + half;           \
            db[le0 * 2] = rb[i].x;                                             \
            db[le1 * 2] = rb[i].y;                                             \
            db[le2 * 2] = rb[i].z;                                             \
            db[le3 * 2] = rb[i].w;                                             \
        }                                                                      \
    }

    LDG_CHUNK(0);
    STS_CHUNK(0);
    __syncthreads();

    for (int it = 0; it < 32; ++it) {
        if (it < 31) LDG_CHUNK((it + 1) * GTK);

        const float* sAc = sm + (it & 1) * STG_FLOATS;
        const float* sBc = sAc + 4096;

#pragma unroll
        for (int ks = 0; ks < 4; ks++) {
            const int lsw = lane ^ ks;
            uint32_t af[4][4];
            uint32_t bf[4][2];
#pragma unroll
            for (int i = 0; i < 4; i++) {
                float4 av = *(const float4*)&sAc[((ks * 8 + wm * 4 + i) * 32 + lsw) * 4];
                af[i][0] = __float_as_uint(av.x);
                af[i][1] = __float_as_uint(av.y);
                af[i][2] = __float_as_uint(av.z);
                af[i][3] = __float_as_uint(av.w);
            }
#pragma unroll
            for (int j = 0; j < 4; j++) {
                float2 bv = *(const float2*)&sBc[((ks * 16 + wn * 4 + j) * 32 + lsw) * 2];
                bf[j][0] = __float_as_uint(bv.x);
                bf[j][1] = __float_as_uint(bv.y);
            }
#pragma unroll
            for (int i = 0; i < 4; i++)
#pragma unroll
                for (int j = 0; j < 4; j++)
                    MMA_TF32(acc[i * 4 + j],
                             af[i][0], af[i][1], af[i][2], af[i][3],
                             bf[j][0], bf[j][1]);
        }

        if (it < 31) STS_CHUNK((it + 1) & 1);
        __syncthreads();
    }

    const int g   = lane >> 2;
    const int cth = lane & 3;
#pragma unroll
    for (int i = 0; i < 4; i++) {
        const int row = m0 + wm * 64 + i * 16 + g;
#pragma unroll
        for (int j = 0; j < 4; j++) {
            const int col = n0 + wn * 32 + j * 8 + cth * 2;
            float2 v0 = make_float2(acc[i * 4 + j][0], acc[i * 4 + j][1]);
            float2 v1 = make_float2(acc[i * 4 + j][2], acc[i * 4 + j][3]);
            if (bias != nullptr) {
                const float b0 = bias[col], b1 = bias[col + 1];
                v0.x += b0; v0.y += b1;
                v1.x += b0; v1.y += b1;
            }
            if (round_out) {
                v0.x = rna_tf32(v0.x); v0.y = rna_tf32(v0.y);
                v1.x = rna_tf32(v1.x); v1.y = rna_tf32(v1.y);
            }
            *(float2*)&C[(size_t)row * DDIM + col]       = v0;
            *(float2*)&C[(size_t)(row + 8) * DDIM + col] = v1;
        }
    }
#undef LDG_CHUNK
#undef STS_CHUNK
}

__global__ __launch_bounds__(256, 1) void qkv_mma_kernel()
{
    const float* Bt = g_Wt + (size_t)blockIdx.z * DDIM * DDIM;
    float* Cp = (blockIdx.z == 0) ? g_Q : (blockIdx.z == 1) ? g_K : g_V;
    gemm_mma_body(g_x, Bt, Cp, nullptr, true);
}

__global__ __launch_bounds__(256, 1) void out_mma_kernel(const float* __restrict__ bo,
                                                         float* __restrict__ out)
{
    gemm_mma_body(g_ctx, g_Wt + 3ull * DDIM * DDIM, out, bo, false);
}

// ===========================================================================
// tf32 mma.sync causal flash attention (R5 structure + occupancy fix).
// CTA: 128 queries x one (b,h), 256 threads (8 warps x 16 q-rows).
// K-block = 64 keys, K/V row-major stride 68 (conflict-free scalar B-frag
// LDS), cp.async double-buffered.
// NEW vs R5: Q A-fragments live in SMEM (fragment-order, one LDS.128 per
// k-step) instead of 32 registers, and __launch_bounds__(256,2) forces
// <=128 regs -> 2 CTAs/SM (occupancy 25%, 4 warps/SMSP).
// Smem: 32KB Q-frags + 2 x 34KB K/V stages = 100KB/CTA.
// ===========================================================================
#define NEG_BIG (-1e30f)
#define AT_STRIDE 68
#define AT_TILE_F (64 * AT_STRIDE)          // 4352 floats
#define AT_STAGE_F (2 * AT_TILE_F)          // K + V per stage = 8704 floats
#define QF_FLOATS 8192                      // 8 warps x 8 ks x 32 lanes x 4
#define ATT_SMEM_BYTES ((QF_FLOATS + 2 * AT_STAGE_F) * 4)   // 102400

__global__ __launch_bounds__(256, 2) void attn_mma_kernel()
{
    extern __shared__ float smf[];
    const uint32_t sb = smem_u32(smf);
    const uint32_t kvb = sb + QF_FLOATS * 4;          // KV staging base
    float* kvf = smf + QF_FLOATS;
    const int tid = threadIdx.x, lane = tid & 31, warp = tid >> 5;
    const int bh = blockIdx.y, b = bh >> 4, h = bh & 15;
    const int qt = (int)gridDim.x - 1 - (int)blockIdx.x;   // heavy first
    const int q0 = qt * 128;
    const int qw0 = q0 + warp * 16;
    const int nb = 2 * qt + 2;
    const int r = lane >> 2, c = lane & 3;

    const float* gq  = g_Q + (size_t)(b * SS + q0) * DDIM + h * DHH;
    const float* gk0 = g_K + (size_t)(b * SS) * DDIM + h * DHH;
    const float* gv0 = g_V + (size_t)(b * SS) * DDIM + h * DHH;

    // ---- stage Q (128 x 64) into KV stage-0 region, build Q-frags in smem ----
#pragma unroll
    for (int i = 0; i < 8; i++) {
        const int ch = tid + i * 256;
        const int row = ch >> 4, c16 = ch & 15;
        cp_async16(kvb + row * 272 + c16 * 16, gq + (size_t)row * DDIM + c16 * 4);
    }
    CP_COMMIT();
    asm volatile("cp.async.wait_group 0;" ::: "memory");
    __syncthreads();

    {
        float* qfw = smf + warp * 1024 + lane * 4;
#pragma unroll
        for (int ks = 0; ks < 8; ks++) {
            const float* qs = kvf + (warp * 16 + r) * AT_STRIDE + ks * 8 + c;
            float4 qv = make_float4(qs[0] * 0.125f, qs[8 * AT_STRIDE] * 0.125f,
                                    qs[4] * 0.125f, qs[8 * AT_STRIDE + 4] * 0.125f);
            *(float4*)&qfw[ks * 128] = qv;
        }
    }
    __syncthreads();

    float O[8][4];
#pragma unroll
    for (int t = 0; t < 8; t++)
#pragma unroll
        for (int e = 0; e < 4; e++) O[t][e] = 0.f;
    float m0v = NEG_BIG, m1v = NEG_BIG, l0v = 0.f, l1v = 0.f;

#define AT_ISSUE(kb, s)                                                            \
    {                                                                              \
        const float* gk = gk0 + (size_t)(kb) * 64 * DDIM;                          \
        const float* gv = gv0 + (size_t)(kb) * 64 * DDIM;                          \
        const uint32_t db = kvb + (uint32_t)(s) * (AT_STAGE_F * 4);                \
        _Pragma("unroll")                                                          \
        for (int i = 0; i < 4; i++) {                                              \
            const int ch = tid + i * 256;                                          \
            const int row = ch >> 4, c16 = ch & 15;                                \
            cp_async16(db + row * 272 + c16 * 16, gk + (size_t)row * DDIM + c16 * 4); \
            cp_async16(db + (AT_TILE_F * 4) + row * 272 + c16 * 16,                \
                       gv + (size_t)row * DDIM + c16 * 4);                         \
        }                                                                          \
    }

    AT_ISSUE(0, 0);
    CP_COMMIT();

    const int l0p = (lane & 28) | ((lane & 3) >> 1);
    const int l2p = l0p + 2;
    const bool odd = (lane & 1) != 0;
    const float* qfw = smf + warp * 1024 + lane * 4;

    for (int kb = 0; kb < nb; kb++) {
        if (kb + 1 < nb) {
            AT_ISSUE(kb + 1, (kb + 1) & 1);
            CP_COMMIT();
            asm volatile("cp.async.wait_group 1;" ::: "memory");
        } else {
            asm volatile("cp.async.wait_group 0;" ::: "memory");
        }
        __syncthreads();

        const int k0 = kb * 64;
        if (k0 <= qw0 + 15) {                       // else fully masked: skip
            const float* Ksm = kvf + (kb & 1) * AT_STAGE_F;
            const float* Vsm = Ksm + AT_TILE_F;

            // ---- S = Q K^T ----
            float s[8][4];
#pragma unroll
            for (int t = 0; t < 8; t++)
#pragma unroll
                for (int e = 0; e < 4; e++) s[t][e] = 0.f;

#pragma unroll
            for (int ks = 0; ks < 8; ks++) {
                const float4 qv = *(const float4*)&qfw[ks * 128];
                const uint32_t a0 = __float_as_uint(qv.x);
                const uint32_t a1 = __float_as_uint(qv.y);
                const uint32_t a2 = __float_as_uint(qv.z);
                const uint32_t a3 = __float_as_uint(qv.w);
#pragma unroll
                for (int nt = 0; nt < 8; nt++) {
                    const float* kp = Ksm + (nt * 8 + r) * AT_STRIDE + ks * 8 + c;
                    const uint32_t b0 = __float_as_uint(kp[0]);
                    const uint32_t b1 = __float_as_uint(kp[4]);
                    MMA_TF32(s[nt], a0, a1, a2, a3, b0, b1);
                }
            }

            // ---- causal mask (only near the diagonal) ----
            if (k0 + 63 > qw0) {
                const int qlo = qw0 + r, qhi = qlo + 8;
#pragma unroll
                for (int nt = 0; nt < 8; nt++) {
                    const int key0 = k0 + nt * 8 + 2 * c;
                    if (key0     > qlo) s[nt][0] = NEG_BIG;
                    if (key0 + 1 > qlo) s[nt][1] = NEG_BIG;
                    if (key0     > qhi) s[nt][2] = NEG_BIG;
                    if (key0 + 1 > qhi) s[nt][3] = NEG_BIG;
                }
            }

            // ---- online softmax ----
            float cl = NEG_BIG, chv = NEG_BIG;
#pragma unroll
            for (int nt = 0; nt < 8; nt++) {
                cl  = fmaxf(cl,  fmaxf(s[nt][0], s[nt][1]));
                chv = fmaxf(chv, fmaxf(s[nt][2], s[nt][3]));
            }
            cl  = fmaxf(cl,  __shfl_xor_sync(0xffffffffu, cl, 1));
            cl  = fmaxf(cl,  __shfl_xor_sync(0xffffffffu, cl, 2));
            chv = fmaxf(chv, __shfl_xor_sync(0xffffffffu, chv, 1));
            chv = fmaxf(chv, __shfl_xor_sync(0xffffffffu, chv, 2));
            const float mn0 = fmaxf(m0v, cl), mn1 = fmaxf(m1v, chv);
            const float corr0 = __expf(m0v - mn0), corr1 = __expf(m1v - mn1);
            m0v = mn0; m1v = mn1;

            float sl = 0.f, sh = 0.f;
#pragma unroll
            for (int nt = 0; nt < 8; nt++) {
                s[nt][0] = __expf(s[nt][0] - mn0); sl += s[nt][0];
                s[nt][1] = __expf(s[nt][1] - mn0); sl += s[nt][1];
                s[nt][2] = __expf(s[nt][2] - mn1); sh += s[nt][2];
                s[nt][3] = __expf(s[nt][3] - mn1); sh += s[nt][3];
            }
            sl += __shfl_xor_sync(0xffffffffu, sl, 1);
            sl += __shfl_xor_sync(0xffffffffu, sl, 2);
            sh += __shfl_xor_sync(0xffffffffu, sh, 1);
            sh += __shfl_xor_sync(0xffffffffu, sh, 2);
            l0v = l0v * corr0 + sl;
            l1v = l1v * corr1 + sh;

#pragma unroll
            for (int nt = 0; nt < 8; nt++) {
                O[nt][0] *= corr0; O[nt][1] *= corr0;
                O[nt][2] *= corr1; O[nt][3] *= corr1;
                s[nt][0] = rna_tf32(s[nt][0]); s[nt][1] = rna_tf32(s[nt][1]);
                s[nt][2] = rna_tf32(s[nt][2]); s[nt][3] = rna_tf32(s[nt][3]);
            }

            // ---- O += P V : shuffle C-frags -> A-frags, then mma ----
#pragma unroll
            for (int ks = 0; ks < 8; ks++) {
                const float e0 = __shfl_sync(0xffffffffu, s[ks][0], l0p);
                const float o0 = __shfl_sync(0xffffffffu, s[ks][1], l0p);
                const float e2 = __shfl_sync(0xffffffffu, s[ks][0], l2p);
                const float o2 = __shfl_sync(0xffffffffu, s[ks][1], l2p);
                const float e1 = __shfl_sync(0xffffffffu, s[ks][2], l0p);
                const float o1 = __shfl_sync(0xffffffffu, s[ks][3], l0p);
                const float e3 = __shfl_sync(0xffffffffu, s[ks][2], l2p);
                const float o3 = __shfl_sync(0xffffffffu, s[ks][3], l2p);
                const uint32_t a0 = __float_as_uint(odd ? o0 : e0);
                const uint32_t a1 = __float_as_uint(odd ? o1 : e1);
                const uint32_t a2 = __float_as_uint(odd ? o2 : e2);
                const uint32_t a3 = __float_as_uint(odd ? o3 : e3);
#pragma unroll
                for (int nt = 0; nt < 8; nt++) {
                    const float* vp = Vsm + (ks * 8 + c) * AT_STRIDE + nt * 8 + r;
                    const uint32_t b0 = __float_as_uint(vp[0]);
                    const uint32_t b1 = __float_as_uint(vp[4 * AT_STRIDE]);
                    MMA_TF32(O[nt], a0, a1, a2, a3, b0, b1);
                }
            }
        }
        __syncthreads();
    }

    // ---- epilogue: normalize, rna-round (feeds tf32 out-proj), store ----
    const float inv0 = 1.f / l0v, inv1 = 1.f / l1v;
    const size_t row0 = (size_t)(b * SS + qw0 + r);
#pragma unroll
    for (int nt = 0; nt < 8; nt++) {
        const int col = h * DHH + nt * 8 + 2 * c;
        float2 w0 = make_float2(rna_tf32(O[nt][0] * inv0), rna_tf32(O[nt][1] * inv0));
        float2 w1 = make_float2(rna_tf32(O[nt][2] * inv1), rna_tf32(O[nt][3] * inv1));
        *(float2*)&g_ctx[row0 * DDIM + col]       = w0;
        *(float2*)&g_ctx[(row0 + 8) * DDIM + col] = w1;
    }
#undef AT_ISSUE
}

// ===========================================================================
extern "C" void kernel_launch(void* const* d_in, const int* in_sizes, int n_in,
                              void* d_out, int out_size)
{
    (void)in_sizes; (void)n_in; (void)out_size;
    const float* x  = (const float*)d_in[0];
    const float* Wq = (const float*)d_in[1];
    const float* Wk = (const float*)d_in[2];
    const float* Wv = (const float*)d_in[3];
    const float* Wo = (const float*)d_in[4];
    const float* bo = (const float*)d_in[5];
    float* out = (float*)d_out;

    cudaFuncSetAttribute(qkv_mma_kernel, cudaFuncAttributeMaxDynamicSharedMemorySize,
                         GEMM_SMEM_BYTES);
    cudaFuncSetAttribute(out_mma_kernel, cudaFuncAttributeMaxDynamicSharedMemorySize,
                         GEMM_SMEM_BYTES);
    cudaFuncSetAttribute(attn_mma_kernel, cudaFuncAttributeMaxDynamicSharedMemorySize,
                         ATT_SMEM_BYTES);

    round_x_kernel<<<(MM * DDIM) / (256 * 4), 256>>>(x);
    transpose_round_kernel<<<dim3(32, 32, 4), dim3(32, 8)>>>(Wq, Wk, Wv, Wo);

    qkv_mma_kernel<<<dim3(DDIM / GTN, MM / GTM, 3), 256, GEMM_SMEM_BYTES>>>();

    attn_mma_kernel<<<dim3(SS / 128, BB * HH), 256, ATT_SMEM_BYTES>>>();

    out_mma_kernel<<<dim3(DDIM / GTN, MM / GTM), 256, GEMM_SMEM_BYTES>>>(bo, out);
}